// round 15
// baseline (speedup 1.0000x reference)
#include <cuda_runtime.h>
#include <cuda_fp16.h>
#include <mma.h>
#include <cstdint>
#include <math.h>

using namespace nvcuda;

// Problem constants
#define BZ   8
#define DI   256
#define DS   512
#define DO   256
#define LL   4096
#define NCH  32
#define CLEN 128
#define LANES (BZ*DS)

// ---------------- scratch ----------------
__device__ float g_Bu[(size_t)LL * BZ * DS];      // (l, b, s) fp32
__device__ float g_last[NCH * LANES];
__device__ float g_carry[NCH * LANES];
__device__ int   g_Dnz;                           // any(D != 0)

// fp16 operands
__device__ __half g_uh[(size_t)BZ * LL * DI];     // [b][l][i]
__device__ __half g_xh[(size_t)LL * BZ * DS];     // [l][b][s]

// fp16 weights, row-major [n][k]
#define WB_OFF 0
#define WC_OFF (512*256)
#define WD_OFF (WC_OFF + 256*512)
#define WTOT   (WD_OFF + 256*256)
__device__ __half g_wh[WTOT];

__device__ __forceinline__ float softplus_f(float x) {
    return fmaxf(x, 0.f) + log1pf(expf(-fabsf(x)));
}

// ---------------- cp.async helpers ----------------
__device__ __forceinline__ void cp16(uint32_t saddr, const void* g) {
    asm volatile("cp.async.cg.shared.global [%0], [%1], 16;" :: "r"(saddr), "l"(g));
}
#define CP_COMMIT()    asm volatile("cp.async.commit_group;" ::: "memory")
#define CP_WAIT_PIPE() asm volatile("cp.async.wait_group 1;" ::: "memory")

// ---------------- smem layout: 3-stage ring, KC=32, 128x128 block tile ------
#define KC 32
#define NSTG 3
#define LDS_T 40                          // padded ld (elements): 80B rows
#define ST_A 0
#define ST_B 10240                        // 128 * 80
#define STAGE_BYTES 20480
#define SMEM_BYTES (NSTG * STAGE_BYTES)   // 61440
#define LDE 132                           // epilogue fp32 ld

// Copy one 128-row x 32-col fp16 tile into padded smem (2 threads/row, 256 thr).
__device__ __forceinline__ void load_tile(uint32_t sbase, const __half* __restrict__ src,
                                          size_t gbase, int gstride, int tid) {
    const int row = tid >> 1, seg = tid & 1;
    const uint32_t sa = sbase + row * (LDS_T * 2) + seg * 32;
    const __half* gp = src + gbase + (size_t)row * gstride + seg * 16;
    cp16(sa, gp);
    cp16(sa + 16, gp + 8);
}

// ---------------- prep ----------------
__global__ void zflag_kernel() { g_Dnz = 0; }

__global__ void prep_kernel(const float* __restrict__ Bm, const float* __restrict__ Cm,
                            const float* __restrict__ Dm) {
    int i = blockIdx.x * 256 + threadIdx.x;
    if (i >= WTOT) return;
    float v = (i < WC_OFF) ? Bm[i] : (i < WD_OFF ? Cm[i - WC_OFF] : Dm[i - WD_OFF]);
    g_wh[i] = __float2half_rn(v);
    if (i >= WD_OFF) {
        unsigned any = __ballot_sync(__activemask(), v != 0.f);
        if ((threadIdx.x & 31) == 0 && any) atomicOr(&g_Dnz, 1);
    }
}

// ---------------- usplit: u[b][i][l] -> fp16 [b][l][i] ----------------
__global__ __launch_bounds__(256) void usplit_kernel(const float* __restrict__ u) {
    __shared__ float t[32][33];
    const int tx = threadIdx.x & 31, ty = threadIdx.x >> 5;
    const int l0 = blockIdx.x * 32, i0 = blockIdx.y * 32, b = blockIdx.z;
    #pragma unroll
    for (int q = 0; q < 4; q++)
        t[ty + 8 * q][tx] = u[((size_t)b * DI + i0 + ty + 8 * q) * LL + l0 + tx];
    __syncthreads();
    #pragma unroll
    for (int q = 0; q < 4; q++) {
        const int l = l0 + ty + 8 * q;
        g_uh[((size_t)b * LL + l) * DI + i0 + tx] = __float2half_rn(t[tx][ty + 8 * q]);
    }
}

// ---------------- GEMM compute body: 32x64 warp tile, one KC=32 chunk --------
#define COMPUTE_CHUNK(sm)                                                                 \
    do {                                                                                  \
        __half* As = (__half*)((sm) + ST_A);                                              \
        __half* Bs = (__half*)((sm) + ST_B);                                              \
        _Pragma("unroll")                                                                 \
        for (int ks = 0; ks < KC; ks += 16) {                                             \
            wmma::fragment<wmma::matrix_a, 16, 16, 16, __half, wmma::row_major> af[2];    \
            _Pragma("unroll")                                                             \
            for (int i = 0; i < 2; i++)                                                   \
                wmma::load_matrix_sync(af[i], As + (wm * 32 + i * 16) * LDS_T + ks, LDS_T);\
            _Pragma("unroll")                                                             \
            for (int j = 0; j < 4; j++) {                                                 \
                wmma::fragment<wmma::matrix_b, 16, 16, 16, __half, wmma::col_major> bf;   \
                wmma::load_matrix_sync(bf, Bs + (wn * 64 + j * 16) * LDS_T + ks, LDS_T);  \
                _Pragma("unroll")                                                         \
                for (int i = 0; i < 2; i++)                                               \
                    wmma::mma_sync(acc[i][j], af[i], bf, acc[i][j]);                      \
            }                                                                             \
        }                                                                                 \
    } while (0)

// ---------------- GEMM1 + fused local scan ----------------
// Block tile: l in [l0, l0+128) == scan chunk blockIdx.x, s in [n0, n0+128), batch b.
__global__ __launch_bounds__(256, 3) void gemm1_wmma(const float* __restrict__ Aun) {
    extern __shared__ char smem[];
    const uint32_t sb = (uint32_t)__cvta_generic_to_shared(smem);
    const int tid = threadIdx.x, wid = tid >> 5;
    const int l0 = blockIdx.x * 128, n0 = blockIdx.y * 128, b = blockIdx.z;
    const int wm = wid & 3, wn = wid >> 2;          // 4x2 warps, 32x64 tiles

    wmma::fragment<wmma::accumulator, 16, 16, 16, float> acc[2][4];
    #pragma unroll
    for (int i = 0; i < 2; i++)
        #pragma unroll
        for (int j = 0; j < 4; j++) wmma::fill_fragment(acc[i][j], 0.f);

    const size_t aB = ((size_t)b * LL + l0) * DI;
    const size_t bB = (size_t)n0 * DI;
    const int NC = DI / KC;   // 8

    #pragma unroll
    for (int s = 0; s < NSTG - 1; s++) {
        uint32_t st = sb + s * STAGE_BYTES;
        load_tile(st + ST_A, g_uh, aB + s * KC, DI, tid);
        load_tile(st + ST_B, g_wh + WB_OFF, bB + s * KC, DI, tid);
        CP_COMMIT();
    }

    for (int c = 0; c < NC; c++) {
        CP_WAIT_PIPE();
        __syncthreads();
        int nc = c + NSTG - 1;
        if (nc < NC) {
            uint32_t st = sb + (nc % NSTG) * STAGE_BYTES;
            load_tile(st + ST_A, g_uh, aB + nc * KC, DI, tid);
            load_tile(st + ST_B, g_wh + WB_OFF, bB + nc * KC, DI, tid);
        }
        CP_COMMIT();
        COMPUTE_CHUNK(smem + (c % NSTG) * STAGE_BYTES);
    }

    // direct store Bu (scanC re-reads it)
    #pragma unroll
    for (int i = 0; i < 2; i++)
        #pragma unroll
        for (int j = 0; j < 4; j++) {
            float* out = g_Bu + (size_t)(l0 + wm * 32 + i * 16) * (BZ * DS)
                              + (size_t)b * DS + n0 + wn * 64 + j * 16;
            wmma::store_matrix_sync(out, acc[i][j], BZ * DS, wmma::mem_row_major);
        }

    // fused local scan (scanA): x_{l+1} = A*x_l + Bu_l over this 128-l chunk.
    // Two passes of 64 l-rows through smem [64][LDE]; 128 threads own s-columns.
    float* stg = (float*)smem;
    float A = 0.f, x = 0.f;
    if (tid < 128) A = -softplus_f(Aun[n0 + tid]);
    #pragma unroll
    for (int h = 0; h < 2; h++) {
        __syncthreads();
        if ((wm >> 1) == h) {
            #pragma unroll
            for (int i = 0; i < 2; i++)
                #pragma unroll
                for (int j = 0; j < 4; j++) {
                    float* sp = stg + (size_t)((wm & 1) * 32 + i * 16) * LDE + wn * 64 + j * 16;
                    wmma::store_matrix_sync(sp, acc[i][j], LDE, wmma::mem_row_major);
                }
        }
        __syncthreads();
        if (tid < 128) {
            #pragma unroll 8
            for (int l = 0; l < 64; l++)
                x = fmaf(A, x, stg[l * LDE + tid]);
        }
    }
    if (tid < 128)
        g_last[blockIdx.x * LANES + b * DS + n0 + tid] = x;
}

// ---------------- GEMM2: Y[b][o][l] = C.x (+ D.u if D != 0) ----------------
__global__ __launch_bounds__(256, 3) void gemm2_wmma(float* __restrict__ Y) {
    extern __shared__ char smem[];
    const uint32_t sb = (uint32_t)__cvta_generic_to_shared(smem);
    const int tid = threadIdx.x, wid = tid >> 5;
    const int l0 = blockIdx.x * 128, o0 = blockIdx.y * 128, b = blockIdx.z;
    const int wm = wid & 3, wn = wid >> 2;

    wmma::fragment<wmma::accumulator, 16, 16, 16, float> acc[2][4];
    #pragma unroll
    for (int i = 0; i < 2; i++)
        #pragma unroll
        for (int j = 0; j < 4; j++) wmma::fill_fragment(acc[i][j], 0.f);

    const size_t aX = ((size_t)l0 * BZ + b) * DS;
    const size_t aU = ((size_t)b * LL + l0) * DI;
    const size_t bC = (size_t)o0 * DS;
    const size_t bD = (size_t)o0 * DI;
    const int NC1 = DS / KC;                         // 16
    const int NC = NC1 + (g_Dnz ? DI / KC : 0);      // 16 or 24

    auto issue = [&](int c, uint32_t st) {
        if (c < NC1) {
            load_tile(st + ST_A, g_xh, aX + c * KC, BZ * DS, tid);
            load_tile(st + ST_B, g_wh + WC_OFF, bC + c * KC, DS, tid);
        } else {
            int k0 = (c - NC1) * KC;
            load_tile(st + ST_A, g_uh, aU + k0, DI, tid);
            load_tile(st + ST_B, g_wh + WD_OFF, bD + k0, DI, tid);
        }
    };

    #pragma unroll
    for (int s = 0; s < NSTG - 1; s++) {
        issue(s, sb + s * STAGE_BYTES);
        CP_COMMIT();
    }

    for (int c = 0; c < NC; c++) {
        CP_WAIT_PIPE();
        __syncthreads();
        int nc = c + NSTG - 1;
        if (nc < NC) issue(nc, sb + (nc % NSTG) * STAGE_BYTES);
        CP_COMMIT();
        COMPUTE_CHUNK(smem + (c % NSTG) * STAGE_BYTES);
    }

    // epilogue: acc (m=l, n=o) -> smem transpose -> Y[b][o][l], two 64-row passes
    float* stg = (float*)smem;                       // [64][LDE] = 33792 B
    #pragma unroll
    for (int h = 0; h < 2; h++) {
        __syncthreads();
        if ((wm >> 1) == h) {
            #pragma unroll
            for (int i = 0; i < 2; i++)
                #pragma unroll
                for (int j = 0; j < 4; j++) {
                    float* sp = stg + (size_t)((wm & 1) * 32 + i * 16) * LDE + wn * 64 + j * 16;
                    wmma::store_matrix_sync(sp, acc[i][j], LDE, wmma::mem_row_major);
                }
        }
        __syncthreads();
        {
            const int o = tid & 127;                 // consecutive threads -> consecutive o
            const int seg = tid >> 7;                // 2 x 32 l-values
            float* yp = Y + ((size_t)b * DO + o0 + o) * LL + l0 + h * 64 + seg * 32;
            const float* sp = stg + (size_t)(seg * 32) * LDE + o;
            #pragma unroll
            for (int q = 0; q < 8; q++) {
                float4 v = make_float4(sp[(q * 4 + 0) * LDE], sp[(q * 4 + 1) * LDE],
                                       sp[(q * 4 + 2) * LDE], sp[(q * 4 + 3) * LDE]);
                *(float4*)(yp + q * 4) = v;
            }
        }
    }
}

// ---------------- scan chain (scanA fused into gemm1) ----------------
__global__ __launch_bounds__(256) void scanB_kernel(const float* __restrict__ Aun,
                                                    const float* __restrict__ h0) {
    const int lane = blockIdx.x * 256 + threadIdx.x;
    const int s = lane & (DS - 1);
    const float A = -softplus_f(Aun[s]);
    float Ap = A;
    #pragma unroll
    for (int i = 0; i < 7; i++) Ap *= Ap;
    float lastv[NCH];
    #pragma unroll
    for (int c = 0; c < NCH; c++) lastv[c] = g_last[c * LANES + lane];
    float h = h0[s];
    #pragma unroll
    for (int c = 0; c < NCH; c++) {
        g_carry[c * LANES + lane] = h;
        h = fmaf(Ap, h, lastv[c]);
    }
}

__global__ __launch_bounds__(256) void scanC_kernel(const float* __restrict__ Aun) {
    const int t = blockIdx.x * 256 + threadIdx.x;
    const int lane4 = (t & (LANES / 4 - 1)) * 4;
    const int c = t / (LANES / 4);
    const int s = lane4 & (DS - 1);
    float4 Av = make_float4(-softplus_f(Aun[s]), -softplus_f(Aun[s + 1]),
                            -softplus_f(Aun[s + 2]), -softplus_f(Aun[s + 3]));
    float4 x = *(const float4*)(g_carry + (size_t)c * LANES + lane4);
    const float* g = g_Bu + (size_t)(c * CLEN) * LANES + lane4;
    __half* xh = g_xh + (size_t)(c * CLEN) * LANES + lane4;
    #pragma unroll 4
    for (int j = 0; j < CLEN; j++) {
        float4 v = *(const float4*)(g + (size_t)j * LANES);
        x.x = fmaf(Av.x, x.x, v.x);
        x.y = fmaf(Av.y, x.y, v.y);
        x.z = fmaf(Av.z, x.z, v.z);
        x.w = fmaf(Av.w, x.w, v.w);
        __half2 p0 = __floats2half2_rn(x.x, x.y);
        __half2 p1 = __floats2half2_rn(x.z, x.w);
        uint2 pk = make_uint2(*(uint32_t*)&p0, *(uint32_t*)&p1);
        *(uint2*)(xh + (size_t)j * LANES) = pk;
    }
}

// ---------------- launch ----------------
extern "C" void kernel_launch(void* const* d_in, const int* in_sizes, int n_in,
                              void* d_out, int out_size) {
    const float* u   = (const float*)d_in[0];
    const float* Aun = (const float*)d_in[1];
    const float* Bm  = (const float*)d_in[2];
    const float* Cm  = (const float*)d_in[3];
    const float* Dm  = (const float*)d_in[4];
    const float* h0  = (const float*)d_in[5];
    float* Y = (float*)d_out;

    cudaFuncSetAttribute(gemm1_wmma, cudaFuncAttributeMaxDynamicSharedMemorySize, SMEM_BYTES);
    cudaFuncSetAttribute(gemm2_wmma, cudaFuncAttributeMaxDynamicSharedMemorySize, SMEM_BYTES);

    zflag_kernel<<<1, 1>>>();
    prep_kernel<<<(WTOT + 255) / 256, 256>>>(Bm, Cm, Dm);

    dim3 gu(LL / 32, DI / 32, BZ);
    usplit_kernel<<<gu, 256>>>(u);

    dim3 g1(LL / 128, DS / 128, BZ);
    gemm1_wmma<<<g1, 256, SMEM_BYTES>>>(Aun);

    scanB_kernel<<<LANES / 256, 256>>>(Aun, h0);
    scanC_kernel<<<(NCH * LANES / 4) / 256, 256>>>(Aun);

    dim3 g2(LL / 128, DO / 128, BZ);
    gemm2_wmma<<<g2, 256, SMEM_BYTES>>>(Y);
}

// round 16
// speedup vs baseline: 1.2249x; 1.2249x over previous
#include <cuda_runtime.h>
#include <cuda_fp16.h>
#include <mma.h>
#include <cstdint>
#include <math.h>

using namespace nvcuda;

// Problem constants
#define BZ   8
#define DI   256
#define DS   512
#define DO   256
#define LL   4096
#define NCH  32
#define CLEN 128
#define LANES (BZ*DS)

// ---------------- scratch ----------------
__device__ float g_Bu[(size_t)LL * BZ * DS];      // (l, b, s) fp32
__device__ float g_last[NCH * LANES];
__device__ float g_carry[NCH * LANES];
__device__ int   g_Dnz = 0;                       // any(D != 0); static zero-init

// fp16 operands
__device__ __half g_uh[(size_t)BZ * LL * DI];     // [b][l][i]
__device__ __half g_xh[(size_t)LL * BZ * DS];     // [l][b][s]

// fp16 weights, row-major [n][k]
#define WB_OFF 0
#define WC_OFF (512*256)
#define WD_OFF (WC_OFF + 256*512)
#define WTOT   (WD_OFF + 256*256)
__device__ __half g_wh[WTOT];

__device__ __forceinline__ float softplus_f(float x) {
    return fmaxf(x, 0.f) + log1pf(expf(-fabsf(x)));
}

// ---------------- cp.async helpers ----------------
__device__ __forceinline__ void cp16(uint32_t saddr, const void* g) {
    asm volatile("cp.async.cg.shared.global [%0], [%1], 16;" :: "r"(saddr), "l"(g));
}
#define CP_COMMIT() asm volatile("cp.async.commit_group;" ::: "memory")
#define CP_WAIT2()  asm volatile("cp.async.wait_group 2;" ::: "memory")

// ---------------- smem layout: 4-stage ring, KC=32 (R11 proven config) ------
#define KC 32
#define NSTG 4
#define LDS_T 40                          // padded ld (elements): 80B rows
#define ST_A 0
#define ST_B 10240                        // 128 * 80
#define STAGE_BYTES 20480
#define SMEM_BYTES (NSTG * STAGE_BYTES)   // 81920

// Copy one 128-row x 32-col fp16 tile into padded smem (2 threads/row).
__device__ __forceinline__ void load_tile(uint32_t sbase, const __half* __restrict__ src,
                                          size_t gbase, int gstride, int tid) {
    const int row = tid >> 1, seg = tid & 1;
    const uint32_t sa = sbase + row * (LDS_T * 2) + seg * 32;
    const __half* gp = src + gbase + (size_t)row * gstride + seg * 16;
    cp16(sa, gp);
    cp16(sa + 16, gp + 8);
}

// ---------------- prep ----------------
__global__ void prep_kernel(const float* __restrict__ Bm, const float* __restrict__ Cm,
                            const float* __restrict__ Dm) {
    int i = blockIdx.x * 256 + threadIdx.x;
    if (i >= WTOT) return;
    float v = (i < WC_OFF) ? Bm[i] : (i < WD_OFF ? Cm[i - WC_OFF] : Dm[i - WD_OFF]);
    g_wh[i] = __float2half_rn(v);
    if (i >= WD_OFF) {
        unsigned any = __ballot_sync(__activemask(), v != 0.f);
        if ((threadIdx.x & 31) == 0 && any) atomicOr(&g_Dnz, 1);
    }
}

// ---------------- usplit: u[b][i][l] -> fp16 [b][l][i] ----------------
__global__ __launch_bounds__(256) void usplit_kernel(const float* __restrict__ u) {
    __shared__ float t[32][33];
    const int tx = threadIdx.x & 31, ty = threadIdx.x >> 5;
    const int l0 = blockIdx.x * 32, i0 = blockIdx.y * 32, b = blockIdx.z;
    #pragma unroll
    for (int q = 0; q < 4; q++)
        t[ty + 8 * q][tx] = u[((size_t)b * DI + i0 + ty + 8 * q) * LL + l0 + tx];
    __syncthreads();
    #pragma unroll
    for (int q = 0; q < 4; q++) {
        const int l = l0 + ty + 8 * q;
        g_uh[((size_t)b * LL + l) * DI + i0 + tx] = __float2half_rn(t[tx][ty + 8 * q]);
    }
}

// ---------------- GEMM compute body (one KC=32 chunk) ----------------
// 32x64 warp tile; bf double-buffered in registers: load bf[j+1] while
// issuing MMAs for bf[j] to hide LDSM latency.
#define COMPUTE_CHUNK(sm)                                                                 \
    do {                                                                                  \
        __half* As = (__half*)((sm) + ST_A);                                              \
        __half* Bs = (__half*)((sm) + ST_B);                                              \
        _Pragma("unroll")                                                                 \
        for (int ks = 0; ks < KC; ks += 16) {                                             \
            wmma::fragment<wmma::matrix_a, 16, 16, 16, __half, wmma::row_major> af[2];    \
            wmma::fragment<wmma::matrix_b, 16, 16, 16, __half, wmma::col_major> bf[2];    \
            _Pragma("unroll")                                                             \
            for (int i = 0; i < 2; i++)                                                   \
                wmma::load_matrix_sync(af[i], As + (wm * 32 + i * 16) * LDS_T + ks, LDS_T);\
            wmma::load_matrix_sync(bf[0], Bs + (wn * 64) * LDS_T + ks, LDS_T);            \
            _Pragma("unroll")                                                             \
            for (int j = 0; j < 4; j++) {                                                 \
                if (j < 3)                                                                \
                    wmma::load_matrix_sync(bf[(j + 1) & 1],                               \
                        Bs + (wn * 64 + (j + 1) * 16) * LDS_T + ks, LDS_T);               \
                _Pragma("unroll")                                                         \
                for (int i = 0; i < 2; i++)                                               \
                    wmma::mma_sync(acc[i][j], af[i], bf[j & 1], acc[i][j]);               \
            }                                                                             \
        }                                                                                 \
    } while (0)

// ---------------- GEMM1: g_Bu[l][b][s] = u . B^T ----------------
__global__ __launch_bounds__(256) void gemm1_wmma(int dummy) {
    extern __shared__ char smem[];
    const uint32_t sb = (uint32_t)__cvta_generic_to_shared(smem);
    const int tid = threadIdx.x, wid = tid >> 5;
    const int l0 = blockIdx.x * 128, n0 = blockIdx.y * 128, b = blockIdx.z;
    const int wm = wid & 3, wn = wid >> 2;          // 4x2 warps, 32x64 tiles

    wmma::fragment<wmma::accumulator, 16, 16, 16, float> acc[2][4];
    #pragma unroll
    for (int i = 0; i < 2; i++)
        #pragma unroll
        for (int j = 0; j < 4; j++) wmma::fill_fragment(acc[i][j], 0.f);

    const size_t aB = ((size_t)b * LL + l0) * DI;
    const size_t bB = (size_t)n0 * DI;
    const int NC = DI / KC;   // 8

    #pragma unroll
    for (int s = 0; s < NSTG - 1; s++) {
        uint32_t st = sb + s * STAGE_BYTES;
        load_tile(st + ST_A, g_uh, aB + s * KC, DI, tid);
        load_tile(st + ST_B, g_wh + WB_OFF, bB + s * KC, DI, tid);
        CP_COMMIT();
    }

    for (int c = 0; c < NC; c++) {
        CP_WAIT2();
        __syncthreads();
        int nc = c + NSTG - 1;
        if (nc < NC) {
            uint32_t st = sb + (nc % NSTG) * STAGE_BYTES;
            load_tile(st + ST_A, g_uh, aB + nc * KC, DI, tid);
            load_tile(st + ST_B, g_wh + WB_OFF, bB + nc * KC, DI, tid);
        }
        CP_COMMIT();
        COMPUTE_CHUNK(smem + (c % NSTG) * STAGE_BYTES);
    }

    #pragma unroll
    for (int i = 0; i < 2; i++)
        #pragma unroll
        for (int j = 0; j < 4; j++) {
            float* out = g_Bu + (size_t)(l0 + wm * 32 + i * 16) * (BZ * DS)
                              + (size_t)b * DS + n0 + wn * 64 + j * 16;
            wmma::store_matrix_sync(out, acc[i][j], BZ * DS, wmma::mem_row_major);
        }
}

// ---------------- GEMM2: Y[b][o][l] = C.x (+ D.u if D != 0) ----------------
#define LDE 136
__global__ __launch_bounds__(256) void gemm2_wmma(float* __restrict__ Y) {
    extern __shared__ char smem[];
    const uint32_t sb = (uint32_t)__cvta_generic_to_shared(smem);
    const int tid = threadIdx.x, wid = tid >> 5;
    const int l0 = blockIdx.x * 128, o0 = blockIdx.y * 128, b = blockIdx.z;
    const int wm = wid & 3, wn = wid >> 2;

    wmma::fragment<wmma::accumulator, 16, 16, 16, float> acc[2][4];
    #pragma unroll
    for (int i = 0; i < 2; i++)
        #pragma unroll
        for (int j = 0; j < 4; j++) wmma::fill_fragment(acc[i][j], 0.f);

    const size_t aX = ((size_t)l0 * BZ + b) * DS;
    const size_t aU = ((size_t)b * LL + l0) * DI;
    const size_t bC = (size_t)o0 * DS;
    const size_t bD = (size_t)o0 * DI;
    const int NC1 = DS / KC;                         // 16
    const int NC = NC1 + (g_Dnz ? DI / KC : 0);      // 16 or 24

    auto issue = [&](int c, uint32_t st) {
        if (c < NC1) {
            load_tile(st + ST_A, g_xh, aX + c * KC, BZ * DS, tid);
            load_tile(st + ST_B, g_wh + WC_OFF, bC + c * KC, DS, tid);
        } else {
            int k0 = (c - NC1) * KC;
            load_tile(st + ST_A, g_uh, aU + k0, DI, tid);
            load_tile(st + ST_B, g_wh + WD_OFF, bD + k0, DI, tid);
        }
    };

    #pragma unroll
    for (int s = 0; s < NSTG - 1; s++) {
        issue(s, sb + s * STAGE_BYTES);
        CP_COMMIT();
    }

    for (int c = 0; c < NC; c++) {
        CP_WAIT2();
        __syncthreads();
        int nc = c + NSTG - 1;
        if (nc < NC) issue(nc, sb + (nc % NSTG) * STAGE_BYTES);
        CP_COMMIT();
        COMPUTE_CHUNK(smem + (c % NSTG) * STAGE_BYTES);
    }

    // epilogue: acc (m=l, n=o) -> smem transpose -> Y[b][o][l] (l contiguous)
    __syncthreads();
    float* stg = (float*)smem;                       // [128][136] fp32 = 69632 B
    #pragma unroll
    for (int i = 0; i < 2; i++)
        #pragma unroll
        for (int j = 0; j < 4; j++) {
            float* sp = stg + (size_t)(wm * 32 + i * 16) * LDE + wn * 64 + j * 16;
            wmma::store_matrix_sync(sp, acc[i][j], LDE, wmma::mem_row_major);
        }
    __syncthreads();
    {
        const int o = tid >> 1;                      // 0..127
        const int half = tid & 1;
        float* yp = Y + ((size_t)b * DO + o0 + o) * LL + l0 + half * 64;
        const float* sp = stg + (size_t)(half * 64) * LDE + o;
        #pragma unroll
        for (int q = 0; q < 16; q++) {
            float4 v = make_float4(sp[(q * 4 + 0) * LDE], sp[(q * 4 + 1) * LDE],
                                   sp[(q * 4 + 2) * LDE], sp[(q * 4 + 3) * LDE]);
            *(float4*)(yp + q * 4) = v;
        }
    }
}

// ---------------- scan: 4 lanes per thread (R11 proven) ----------------
__global__ __launch_bounds__(256) void scanA_kernel(const float* __restrict__ Aun) {
    const int t = blockIdx.x * 256 + threadIdx.x;
    const int lane4 = (t & (LANES / 4 - 1)) * 4;
    const int c = t / (LANES / 4);
    const int s = lane4 & (DS - 1);
    float4 Av = make_float4(-softplus_f(Aun[s]), -softplus_f(Aun[s + 1]),
                            -softplus_f(Aun[s + 2]), -softplus_f(Aun[s + 3]));
    const float* g = g_Bu + (size_t)(c * CLEN) * LANES + lane4;
    float4 x = make_float4(0.f, 0.f, 0.f, 0.f);
    #pragma unroll 8
    for (int j = 0; j < CLEN; j++) {
        float4 v = *(const float4*)(g + (size_t)j * LANES);
        x.x = fmaf(Av.x, x.x, v.x);
        x.y = fmaf(Av.y, x.y, v.y);
        x.z = fmaf(Av.z, x.z, v.z);
        x.w = fmaf(Av.w, x.w, v.w);
    }
    *(float4*)(g_last + (size_t)c * LANES + lane4) = x;
}

__global__ __launch_bounds__(256) void scanB_kernel(const float* __restrict__ Aun,
                                                    const float* __restrict__ h0) {
    const int lane = blockIdx.x * 256 + threadIdx.x;
    const int s = lane & (DS - 1);
    const float A = -softplus_f(Aun[s]);
    float Ap = A;
    #pragma unroll
    for (int i = 0; i < 7; i++) Ap *= Ap;
    float lastv[NCH];
    #pragma unroll
    for (int c = 0; c < NCH; c++) lastv[c] = g_last[c * LANES + lane];
    float h = h0[s];
    #pragma unroll
    for (int c = 0; c < NCH; c++) {
        g_carry[c * LANES + lane] = h;
        h = fmaf(Ap, h, lastv[c]);
    }
}

__global__ __launch_bounds__(256) void scanC_kernel(const float* __restrict__ Aun) {
    const int t = blockIdx.x * 256 + threadIdx.x;
    const int lane4 = (t & (LANES / 4 - 1)) * 4;
    const int c = t / (LANES / 4);
    const int s = lane4 & (DS - 1);
    float4 Av = make_float4(-softplus_f(Aun[s]), -softplus_f(Aun[s + 1]),
                            -softplus_f(Aun[s + 2]), -softplus_f(Aun[s + 3]));
    float4 x = *(const float4*)(g_carry + (size_t)c * LANES + lane4);
    const float* g = g_Bu + (size_t)(c * CLEN) * LANES + lane4;
    __half* xh = g_xh + (size_t)(c * CLEN) * LANES + lane4;
    #pragma unroll 4
    for (int j = 0; j < CLEN; j++) {
        float4 v = *(const float4*)(g + (size_t)j * LANES);
        x.x = fmaf(Av.x, x.x, v.x);
        x.y = fmaf(Av.y, x.y, v.y);
        x.z = fmaf(Av.z, x.z, v.z);
        x.w = fmaf(Av.w, x.w, v.w);
        __half2 p0 = __floats2half2_rn(x.x, x.y);
        __half2 p1 = __floats2half2_rn(x.z, x.w);
        uint2 pk = make_uint2(*(uint32_t*)&p0, *(uint32_t*)&p1);
        *(uint2*)(xh + (size_t)j * LANES) = pk;
    }
}

// ---------------- launch ----------------
extern "C" void kernel_launch(void* const* d_in, const int* in_sizes, int n_in,
                              void* d_out, int out_size) {
    const float* u   = (const float*)d_in[0];
    const float* Aun = (const float*)d_in[1];
    const float* Bm  = (const float*)d_in[2];
    const float* Cm  = (const float*)d_in[3];
    const float* Dm  = (const float*)d_in[4];
    const float* h0  = (const float*)d_in[5];
    float* Y = (float*)d_out;

    cudaFuncSetAttribute(gemm1_wmma, cudaFuncAttributeMaxDynamicSharedMemorySize, SMEM_BYTES);
    cudaFuncSetAttribute(gemm2_wmma, cudaFuncAttributeMaxDynamicSharedMemorySize, SMEM_BYTES);

    prep_kernel<<<(WTOT + 255) / 256, 256>>>(Bm, Cm, Dm);

    dim3 gu(LL / 32, DI / 32, BZ);
    usplit_kernel<<<gu, 256>>>(u);

    dim3 g1(LL / 128, DS / 128, BZ);
    gemm1_wmma<<<g1, 256, SMEM_BYTES>>>(0);

    scanA_kernel<<<(NCH * LANES / 4) / 256, 256>>>(Aun);
    scanB_kernel<<<LANES / 256, 256>>>(Aun, h0);
    scanC_kernel<<<(NCH * LANES / 4) / 256, 256>>>(Aun);

    dim3 g2(LL / 128, DO / 128, BZ);
    gemm2_wmma<<<g2, 256, SMEM_BYTES>>>(Y);
}

// round 17
// speedup vs baseline: 1.5566x; 1.2708x over previous
#include <cuda_runtime.h>
#include <cuda_fp16.h>
#include <mma.h>
#include <cstdint>
#include <math.h>

using namespace nvcuda;

// Problem constants
#define BZ   8
#define DI   256
#define DS   512
#define DO   256
#define LL   4096
#define NCH  64
#define CLEN 64
#define LANES (BZ*DS)

// ---------------- scratch ----------------
__device__ __half g_Buh[(size_t)LL * BZ * DS];    // (l, b, s) fp16 Bu
__device__ float g_last[NCH * LANES];
__device__ float g_carry[NCH * LANES];
__device__ int   g_Dnz = 0;                       // any(D != 0)

// fp16 operands
__device__ __half g_uh[(size_t)BZ * LL * DI];     // [b][l][i]
__device__ __half g_xh[(size_t)LL * BZ * DS];     // [l][b][s]

// fp16 weights, row-major [n][k]
#define WB_OFF 0
#define WC_OFF (512*256)
#define WD_OFF (WC_OFF + 256*512)
#define WTOT   (WD_OFF + 256*256)
__device__ __half g_wh[WTOT];

__device__ __forceinline__ float softplus_f(float x) {
    return fmaxf(x, 0.f) + log1pf(expf(-fabsf(x)));
}

// ---------------- cp.async helpers ----------------
__device__ __forceinline__ void cp16(uint32_t saddr, const void* g) {
    asm volatile("cp.async.cg.shared.global [%0], [%1], 16;" :: "r"(saddr), "l"(g));
}
#define CP_COMMIT() asm volatile("cp.async.commit_group;" ::: "memory")
#define CP_WAIT2()  asm volatile("cp.async.wait_group 2;" ::: "memory")

// ---------------- smem layout: 4-stage ring, KC=32 (proven config) ----------
#define KC 32
#define NSTG 4
#define LDS_T 40                          // padded ld (elements): 80B rows
#define ST_A 0
#define ST_B 10240                        // 128 * 80
#define STAGE_BYTES 20480
#define SMEM_BYTES (NSTG * STAGE_BYTES)   // 81920
#define LDE 136                           // epilogue fp32 ld

// Copy one 128-row x 32-col fp16 tile into padded smem (2 threads/row).
__device__ __forceinline__ void load_tile(uint32_t sbase, const __half* __restrict__ src,
                                          size_t gbase, int gstride, int tid) {
    const int row = tid >> 1, seg = tid & 1;
    const uint32_t sa = sbase + row * (LDS_T * 2) + seg * 32;
    const __half* gp = src + gbase + (size_t)row * gstride + seg * 16;
    cp16(sa, gp);
    cp16(sa + 16, gp + 8);
}

// ---------------- prep ----------------
__global__ void prep_kernel(const float* __restrict__ Bm, const float* __restrict__ Cm,
                            const float* __restrict__ Dm) {
    int i = blockIdx.x * 256 + threadIdx.x;
    if (i >= WTOT) return;
    float v = (i < WC_OFF) ? Bm[i] : (i < WD_OFF ? Cm[i - WC_OFF] : Dm[i - WD_OFF]);
    g_wh[i] = __float2half_rn(v);
    if (i >= WD_OFF) {
        unsigned any = __ballot_sync(__activemask(), v != 0.f);
        if ((threadIdx.x & 31) == 0 && any) atomicOr(&g_Dnz, 1);
    }
}

// ---------------- usplit: u[b][i][l] -> fp16 [b][l][i] ----------------
__global__ __launch_bounds__(256) void usplit_kernel(const float* __restrict__ u) {
    __shared__ float t[32][33];
    const int tx = threadIdx.x & 31, ty = threadIdx.x >> 5;
    const int l0 = blockIdx.x * 32, i0 = blockIdx.y * 32, b = blockIdx.z;
    #pragma unroll
    for (int q = 0; q < 4; q++)
        t[ty + 8 * q][tx] = u[((size_t)b * DI + i0 + ty + 8 * q) * LL + l0 + tx];
    __syncthreads();
    #pragma unroll
    for (int q = 0; q < 4; q++) {
        const int l = l0 + ty + 8 * q;
        g_uh[((size_t)b * LL + l) * DI + i0 + tx] = __float2half_rn(t[tx][ty + 8 * q]);
    }
}

// ---------------- GEMM compute body (one KC=32 chunk), 32x64 warp tile ------
#define COMPUTE_CHUNK(sm)                                                                 \
    do {                                                                                  \
        __half* As = (__half*)((sm) + ST_A);                                              \
        __half* Bs = (__half*)((sm) + ST_B);                                              \
        _Pragma("unroll")                                                                 \
        for (int ks = 0; ks < KC; ks += 16) {                                             \
            wmma::fragment<wmma::matrix_a, 16, 16, 16, __half, wmma::row_major> af[2];    \
            _Pragma("unroll")                                                             \
            for (int i = 0; i < 2; i++)                                                   \
                wmma::load_matrix_sync(af[i], As + (wm * 32 + i * 16) * LDS_T + ks, LDS_T);\
            _Pragma("unroll")                                                             \
            for (int j = 0; j < 4; j++) {                                                 \
                wmma::fragment<wmma::matrix_b, 16, 16, 16, __half, wmma::col_major> bf;   \
                wmma::load_matrix_sync(bf, Bs + (wn * 64 + j * 16) * LDS_T + ks, LDS_T);  \
                _Pragma("unroll")                                                         \
                for (int i = 0; i < 2; i++)                                               \
                    wmma::mma_sync(acc[i][j], af[i], bf, acc[i][j]);                      \
            }                                                                             \
        }                                                                                 \
    } while (0)

// ---------------- GEMM1: g_Buh[l][b][s] = fp16( u . B^T ) ----------------
__global__ __launch_bounds__(256) void gemm1_wmma(int dummy) {
    extern __shared__ char smem[];
    const uint32_t sb = (uint32_t)__cvta_generic_to_shared(smem);
    const int tid = threadIdx.x, wid = tid >> 5;
    const int l0 = blockIdx.x * 128, n0 = blockIdx.y * 128, b = blockIdx.z;
    const int wm = wid & 3, wn = wid >> 2;          // 4x2 warps, 32x64 tiles

    wmma::fragment<wmma::accumulator, 16, 16, 16, float> acc[2][4];
    #pragma unroll
    for (int i = 0; i < 2; i++)
        #pragma unroll
        for (int j = 0; j < 4; j++) wmma::fill_fragment(acc[i][j], 0.f);

    const size_t aB = ((size_t)b * LL + l0) * DI;
    const size_t bB = (size_t)n0 * DI;
    const int NC = DI / KC;   // 8

    #pragma unroll
    for (int s = 0; s < NSTG - 1; s++) {
        uint32_t st = sb + s * STAGE_BYTES;
        load_tile(st + ST_A, g_uh, aB + s * KC, DI, tid);
        load_tile(st + ST_B, g_wh + WB_OFF, bB + s * KC, DI, tid);
        CP_COMMIT();
    }

    for (int c = 0; c < NC; c++) {
        CP_WAIT2();
        __syncthreads();
        int nc = c + NSTG - 1;
        if (nc < NC) {
            uint32_t st = sb + (nc % NSTG) * STAGE_BYTES;
            load_tile(st + ST_A, g_uh, aB + nc * KC, DI, tid);
            load_tile(st + ST_B, g_wh + WB_OFF, bB + nc * KC, DI, tid);
        }
        CP_COMMIT();
        COMPUTE_CHUNK(smem + (c % NSTG) * STAGE_BYTES);
    }

    // epilogue: acc fp32 -> smem -> fp16 g_Buh (s contiguous)
    __syncthreads();
    float* stg = (float*)smem;                       // [128][136] = 69632 B
    #pragma unroll
    for (int i = 0; i < 2; i++)
        #pragma unroll
        for (int j = 0; j < 4; j++) {
            float* sp = stg + (size_t)(wm * 32 + i * 16) * LDE + wn * 64 + j * 16;
            wmma::store_matrix_sync(sp, acc[i][j], LDE, wmma::mem_row_major);
        }
    __syncthreads();
    {
        const int l = tid >> 1, half = tid & 1;
        __half* op = g_Buh + ((size_t)(l0 + l) * BZ + b) * DS + n0 + half * 64;
        const float* sp = stg + (size_t)l * LDE + half * 64;
        #pragma unroll
        for (int q = 0; q < 8; q++) {
            float4 v0 = *(const float4*)(sp + q * 8);
            float4 v1 = *(const float4*)(sp + q * 8 + 4);
            __half2 h0 = __floats2half2_rn(v0.x, v0.y);
            __half2 h1 = __floats2half2_rn(v0.z, v0.w);
            __half2 h2 = __floats2half2_rn(v1.x, v1.y);
            __half2 h3 = __floats2half2_rn(v1.z, v1.w);
            uint4 pk = make_uint4(*(uint32_t*)&h0, *(uint32_t*)&h1,
                                  *(uint32_t*)&h2, *(uint32_t*)&h3);
            *(uint4*)(op + q * 8) = pk;
        }
    }
}

// ---------------- GEMM2: Y[b][o][l] = C.x (+ D.u if D != 0) ----------------
__global__ __launch_bounds__(256) void gemm2_wmma(float* __restrict__ Y) {
    extern __shared__ char smem[];
    const uint32_t sb = (uint32_t)__cvta_generic_to_shared(smem);
    const int tid = threadIdx.x, wid = tid >> 5;
    const int l0 = blockIdx.x * 128, o0 = blockIdx.y * 128, b = blockIdx.z;
    const int wm = wid & 3, wn = wid >> 2;

    wmma::fragment<wmma::accumulator, 16, 16, 16, float> acc[2][4];
    #pragma unroll
    for (int i = 0; i < 2; i++)
        #pragma unroll
        for (int j = 0; j < 4; j++) wmma::fill_fragment(acc[i][j], 0.f);

    const size_t aX = ((size_t)l0 * BZ + b) * DS;
    const size_t aU = ((size_t)b * LL + l0) * DI;
    const size_t bC = (size_t)o0 * DS;
    const size_t bD = (size_t)o0 * DI;
    const int NC1 = DS / KC;                         // 16
    const int NC = NC1 + (g_Dnz ? DI / KC : 0);      // 16 or 24

    auto issue = [&](int c, uint32_t st) {
        if (c < NC1) {
            load_tile(st + ST_A, g_xh, aX + c * KC, BZ * DS, tid);
            load_tile(st + ST_B, g_wh + WC_OFF, bC + c * KC, DS, tid);
        } else {
            int k0 = (c - NC1) * KC;
            load_tile(st + ST_A, g_uh, aU + k0, DI, tid);
            load_tile(st + ST_B, g_wh + WD_OFF, bD + k0, DI, tid);
        }
    };

    #pragma unroll
    for (int s = 0; s < NSTG - 1; s++) {
        issue(s, sb + s * STAGE_BYTES);
        CP_COMMIT();
    }

    for (int c = 0; c < NC; c++) {
        CP_WAIT2();
        __syncthreads();
        int nc = c + NSTG - 1;
        if (nc < NC) issue(nc, sb + (nc % NSTG) * STAGE_BYTES);
        CP_COMMIT();
        COMPUTE_CHUNK(smem + (c % NSTG) * STAGE_BYTES);
    }

    // epilogue: acc (m=l, n=o) -> smem transpose -> Y[b][o][l] (l contiguous)
    __syncthreads();
    float* stg = (float*)smem;                       // [128][136] fp32 = 69632 B
    #pragma unroll
    for (int i = 0; i < 2; i++)
        #pragma unroll
        for (int j = 0; j < 4; j++) {
            float* sp = stg + (size_t)(wm * 32 + i * 16) * LDE + wn * 64 + j * 16;
            wmma::store_matrix_sync(sp, acc[i][j], LDE, wmma::mem_row_major);
        }
    __syncthreads();
    {
        const int o = tid >> 1;                      // 0..127
        const int half = tid & 1;
        float* yp = Y + ((size_t)b * DO + o0 + o) * LL + l0 + half * 64;
        const float* sp = stg + (size_t)(half * 64) * LDE + o;
        #pragma unroll
        for (int q = 0; q < 16; q++) {
            float4 v = make_float4(sp[(q * 4 + 0) * LDE], sp[(q * 4 + 1) * LDE],
                                   sp[(q * 4 + 2) * LDE], sp[(q * 4 + 3) * LDE]);
            *(float4*)(yp + q * 4) = v;
        }
    }
}

// ---------------- scan: NCH=64 chunks of CLEN=64, 4 lanes/thread ------------
__global__ __launch_bounds__(256) void scanA_kernel(const float* __restrict__ Aun) {
    const int t = blockIdx.x * 256 + threadIdx.x;
    const int lane4 = (t & (LANES / 4 - 1)) * 4;     // LANES/4 = 1024
    const int c = t >> 10;
    const int s = lane4 & (DS - 1);
    float4 Av = make_float4(-softplus_f(Aun[s]), -softplus_f(Aun[s + 1]),
                            -softplus_f(Aun[s + 2]), -softplus_f(Aun[s + 3]));
    const __half* g = g_Buh + (size_t)(c * CLEN) * LANES + lane4;
    float4 x = make_float4(0.f, 0.f, 0.f, 0.f);
    #pragma unroll 8
    for (int j = 0; j < CLEN; j++) {
        uint2 pk = *(const uint2*)(g + (size_t)j * LANES);
        float2 f0 = __half22float2(*(__half2*)&pk.x);
        float2 f1 = __half22float2(*(__half2*)&pk.y);
        x.x = fmaf(Av.x, x.x, f0.x);
        x.y = fmaf(Av.y, x.y, f0.y);
        x.z = fmaf(Av.z, x.z, f1.x);
        x.w = fmaf(Av.w, x.w, f1.y);
    }
    *(float4*)(g_last + (size_t)c * LANES + lane4) = x;
}

__global__ __launch_bounds__(256) void scanB_kernel(const float* __restrict__ Aun,
                                                    const float* __restrict__ h0) {
    const int lane = blockIdx.x * 256 + threadIdx.x;
    const int s = lane & (DS - 1);
    const float A = -softplus_f(Aun[s]);
    float Ap = A;
    #pragma unroll
    for (int i = 0; i < 6; i++) Ap *= Ap;            // A^64 (CLEN=2^6)
    float lastv[NCH];
    #pragma unroll
    for (int c = 0; c < NCH; c++) lastv[c] = g_last[c * LANES + lane];
    float h = h0[s];
    #pragma unroll
    for (int c = 0; c < NCH; c++) {
        g_carry[c * LANES + lane] = h;
        h = fmaf(Ap, h, lastv[c]);
    }
}

__global__ __launch_bounds__(256) void scanC_kernel(const float* __restrict__ Aun) {
    const int t = blockIdx.x * 256 + threadIdx.x;
    const int lane4 = (t & (LANES / 4 - 1)) * 4;
    const int c = t >> 10;
    const int s = lane4 & (DS - 1);
    float4 Av = make_float4(-softplus_f(Aun[s]), -softplus_f(Aun[s + 1]),
                            -softplus_f(Aun[s + 2]), -softplus_f(Aun[s + 3]));
    float4 x = *(const float4*)(g_carry + (size_t)c * LANES + lane4);
    const __half* g = g_Buh + (size_t)(c * CLEN) * LANES + lane4;
    __half* xh = g_xh + (size_t)(c * CLEN) * LANES + lane4;
    #pragma unroll 4
    for (int j = 0; j < CLEN; j++) {
        uint2 pk = *(const uint2*)(g + (size_t)j * LANES);
        float2 f0 = __half22float2(*(__half2*)&pk.x);
        float2 f1 = __half22float2(*(__half2*)&pk.y);
        x.x = fmaf(Av.x, x.x, f0.x);
        x.y = fmaf(Av.y, x.y, f0.y);
        x.z = fmaf(Av.z, x.z, f1.x);
        x.w = fmaf(Av.w, x.w, f1.y);
        __half2 p0 = __floats2half2_rn(x.x, x.y);
        __half2 p1 = __floats2half2_rn(x.z, x.w);
        uint2 ok = make_uint2(*(uint32_t*)&p0, *(uint32_t*)&p1);
        *(uint2*)(xh + (size_t)j * LANES) = ok;
    }
}

// ---------------- launch ----------------
extern "C" void kernel_launch(void* const* d_in, const int* in_sizes, int n_in,
                              void* d_out, int out_size) {
    const float* u   = (const float*)d_in[0];
    const float* Aun = (const float*)d_in[1];
    const float* Bm  = (const float*)d_in[2];
    const float* Cm  = (const float*)d_in[3];
    const float* Dm  = (const float*)d_in[4];
    const float* h0  = (const float*)d_in[5];
    float* Y = (float*)d_out;

    cudaFuncSetAttribute(gemm1_wmma, cudaFuncAttributeMaxDynamicSharedMemorySize, SMEM_BYTES);
    cudaFuncSetAttribute(gemm2_wmma, cudaFuncAttributeMaxDynamicSharedMemorySize, SMEM_BYTES);

    prep_kernel<<<(WTOT + 255) / 256, 256>>>(Bm, Cm, Dm);

    dim3 gu(LL / 32, DI / 32, BZ);
    usplit_kernel<<<gu, 256>>>(u);

    dim3 g1(LL / 128, DS / 128, BZ);
    gemm1_wmma<<<g1, 256, SMEM_BYTES>>>(0);

    scanA_kernel<<<(NCH * LANES / 4) / 256, 256>>>(Aun);
    scanB_kernel<<<LANES / 256, 256>>>(Aun, h0);
    scanC_kernel<<<(NCH * LANES / 4) / 256, 256>>>(Aun);

    dim3 g2(LL / 128, DO / 128, BZ);
    gemm2_wmma<<<g2, 256, SMEM_BYTES>>>(Y);
}